// round 9
// baseline (speedup 1.0000x reference)
#include <cuda_runtime.h>
#include <cuda_fp16.h>
#include <mma.h>
#include <math.h>
#include <cstdint>

using namespace nvcuda;

#define S_LEN 2048
#define DM    1024
#define NH    16
#define HD    64

// Scratch (allocation-guard rules: __device__ globals).
__device__ __half g_xh[S_LEN * DM];
__device__ __half g_wh[3][DM * DM];
__device__ __half g_qh[S_LEN * DM];
__device__ __half g_kh[S_LEN * DM];
__device__ __half g_vh[S_LEN * DM];
__device__ __half g_eh[(size_t)NH * S_LEN * S_LEN];  // unnormalized exp(scores), half
__device__ float  g_psum[NH * S_LEN * 16];           // per-(row, ktile) partial sums

// ---------------------------------------------------------------------------
// fp32 -> fp16 converters.
// ---------------------------------------------------------------------------
__device__ __forceinline__ void cvt4(const float* __restrict__ src,
                                     __half* __restrict__ dst, size_t i)
{
    float4 v = ((const float4*)src)[i];
    __half2 a = __floats2half2_rn(v.x, v.y);
    __half2 b = __floats2half2_rn(v.z, v.w);
    uint2 u;
    u.x = *(const uint32_t*)&a;
    u.y = *(const uint32_t*)&b;
    ((uint2*)dst)[i] = u;
}

__global__ __launch_bounds__(256) void cvt_x_kernel(const float* __restrict__ X)
{
    cvt4(X, g_xh, (size_t)blockIdx.x * 256 + threadIdx.x);
}

__global__ __launch_bounds__(256) void cvt_w_kernel(
    const float* __restrict__ Wq, const float* __restrict__ Wk,
    const float* __restrict__ Wv)
{
    const float* src = (blockIdx.z == 0) ? Wq : (blockIdx.z == 1) ? Wk : Wv;
    cvt4(src, g_wh[blockIdx.z], (size_t)blockIdx.x * 256 + threadIdx.x);
}

// ---------------------------------------------------------------------------
// Kernel 1: QKV projection, fp16 in / fp32 accum / fp16 out (smem-staged).
// BM=128, BN=64, BK=32. 256 threads = 8 warps (4x2), warp tile 32x32.
// ---------------------------------------------------------------------------
__global__ __launch_bounds__(256) void qkv_gemm_kernel()
{
    constexpr int BM = 128, BN = 64, BK = 32;
    const __half* W = g_wh[blockIdx.z];
    __half*       Y = (blockIdx.z == 0) ? g_qh : (blockIdx.z == 1) ? g_kh : g_vh;

    __shared__ __align__(16) __half As[BM][BK + 8];
    __shared__ __align__(16) __half Bs[BK][BN + 8];
    __shared__ __align__(16) float  Cs[BM][BN + 4];

    const int tid  = threadIdx.x;
    const int warp = tid >> 5;
    const int wm   = warp & 3;
    const int wn   = warp >> 2;

    const int row0 = blockIdx.y * BM;
    const int col0 = blockIdx.x * BN;

    wmma::fragment<wmma::accumulator, 16, 16, 16, float> acc[2][2];
    #pragma unroll
    for (int i = 0; i < 2; i++)
        #pragma unroll
        for (int j = 0; j < 2; j++)
            wmma::fill_fragment(acc[i][j], 0.0f);

    for (int k0 = 0; k0 < DM; k0 += BK) {
        #pragma unroll
        for (int it = 0; it < 2; it++) {
            int idx = tid + it * 256;
            int r = idx >> 2, c = idx & 3;
            *(int4*)&As[r][c * 8] =
                *(const int4*)&g_xh[(size_t)(row0 + r) * DM + k0 + c * 8];
        }
        {
            int r = tid >> 3, c = tid & 7;
            *(int4*)&Bs[r][c * 8] =
                *(const int4*)&W[(size_t)(k0 + r) * DM + col0 + c * 8];
        }
        __syncthreads();

        #pragma unroll
        for (int kk = 0; kk < BK; kk += 16) {
            wmma::fragment<wmma::matrix_a, 16, 16, 16, __half, wmma::row_major> a[2];
            wmma::fragment<wmma::matrix_b, 16, 16, 16, __half, wmma::row_major> b[2];
            #pragma unroll
            for (int i = 0; i < 2; i++)
                wmma::load_matrix_sync(a[i], &As[wm * 32 + i * 16][kk], BK + 8);
            #pragma unroll
            for (int j = 0; j < 2; j++)
                wmma::load_matrix_sync(b[j], &Bs[kk][wn * 32 + j * 16], BN + 8);
            #pragma unroll
            for (int i = 0; i < 2; i++)
                #pragma unroll
                for (int j = 0; j < 2; j++)
                    wmma::mma_sync(acc[i][j], a[i], b[j], acc[i][j]);
        }
        __syncthreads();
    }

    #pragma unroll
    for (int i = 0; i < 2; i++)
        #pragma unroll
        for (int j = 0; j < 2; j++)
            wmma::store_matrix_sync(&Cs[wm * 32 + i * 16][wn * 32 + j * 16],
                                    acc[i][j], BN + 4, wmma::mem_row_major);
    __syncthreads();

    #pragma unroll
    for (int it = 0; it < 8; it++) {
        int idx = tid + it * 256;
        int r = idx >> 4, c4 = idx & 15;
        float4 v = *(const float4*)&Cs[r][c4 * 4];
        __half2 h0 = __floats2half2_rn(v.x, v.y);
        __half2 h1 = __floats2half2_rn(v.z, v.w);
        uint2 u;
        u.x = *(const uint32_t*)&h0;
        u.y = *(const uint32_t*)&h1;
        *(uint2*)&Y[(size_t)(row0 + r) * DM + col0 + c4 * 4] = u;
    }
}

// ---------------------------------------------------------------------------
// Kernel 2: e = exp(q.k/8) (unnormalized), written as HALF to g_eh.
// 128x128 tile, 8 warps (4x2), warp tile 32x64. exp applied in registers.
// Single merged epilogue: smem fp32 stage read once; chunk sums reduced via
// shfl across the 16-lane row group. Emits per-(row, ktile) partial sums.
// ---------------------------------------------------------------------------
__global__ __launch_bounds__(256) void scores_exp_kernel()
{
    const int h = blockIdx.z;
    __shared__ __align__(16) union {
        struct { __half Q[128][HD + 8]; __half K[128][HD + 8]; } in;
        float S[128][132];
    } u;

    const int tid  = threadIdx.x;
    const int warp = tid >> 5;
    const int wm   = warp & 3;   // 4 strips of 32 q-rows
    const int wn   = warp >> 2;  // 2 strips of 64 k-cols

    const int qrow0 = blockIdx.y * 128;
    const int krow0 = blockIdx.x * 128;
    const __half* qp = g_qh + h * HD;
    const __half* kp = g_kh + h * HD;

    #pragma unroll
    for (int it = 0; it < 4; it++) {
        int idx = tid + it * 256;
        int r = idx >> 3, c = idx & 7;
        *(int4*)&u.in.Q[r][c * 8] =
            *(const int4*)&qp[(size_t)(qrow0 + r) * DM + c * 8];
        *(int4*)&u.in.K[r][c * 8] =
            *(const int4*)&kp[(size_t)(krow0 + r) * DM + c * 8];
    }
    __syncthreads();

    wmma::fragment<wmma::accumulator, 16, 16, 16, float> acc[2][4];
    #pragma unroll
    for (int i = 0; i < 2; i++)
        #pragma unroll
        for (int j = 0; j < 4; j++)
            wmma::fill_fragment(acc[i][j], 0.0f);

    #pragma unroll
    for (int kk = 0; kk < HD; kk += 16) {
        wmma::fragment<wmma::matrix_a, 16, 16, 16, __half, wmma::row_major> a[2];
        wmma::fragment<wmma::matrix_b, 16, 16, 16, __half, wmma::col_major> b[4];
        #pragma unroll
        for (int i = 0; i < 2; i++)
            wmma::load_matrix_sync(a[i], &u.in.Q[wm * 32 + i * 16][kk], HD + 8);
        #pragma unroll
        for (int j = 0; j < 4; j++)
            wmma::load_matrix_sync(b[j], &u.in.K[wn * 64 + j * 16][kk], HD + 8);
        #pragma unroll
        for (int i = 0; i < 2; i++)
            #pragma unroll
            for (int j = 0; j < 4; j++)
                wmma::mma_sync(acc[i][j], a[i], b[j], acc[i][j]);
    }

    // exp in registers, then stage fp32 (Q/K tiles are dead -> reuse smem).
    __syncthreads();
    #pragma unroll
    for (int i = 0; i < 2; i++)
        #pragma unroll
        for (int j = 0; j < 4; j++) {
            #pragma unroll
            for (int e = 0; e < acc[i][j].num_elements; e++)
                acc[i][j].x[e] = __expf(acc[i][j].x[e] * 0.125f);
            wmma::store_matrix_sync(&u.S[wm * 32 + i * 16][wn * 64 + j * 16],
                                    acc[i][j], 132, wmma::mem_row_major);
        }
    __syncthreads();

    // Merged epilogue: one smem read pass; half convert + gmem write + shfl sum.
    __half* outp = g_eh + (size_t)h * S_LEN * S_LEN;
    #pragma unroll
    for (int it = 0; it < 8; it++) {
        int idx = tid + it * 256;        // 128 rows x 16 chunks of 8
        int r = idx >> 4, c = idx & 15;
        float4 v0 = *(const float4*)&u.S[r][c * 8];
        float4 v1 = *(const float4*)&u.S[r][c * 8 + 4];
        __half2 h0 = __floats2half2_rn(v0.x, v0.y);
        __half2 h1 = __floats2half2_rn(v0.z, v0.w);
        __half2 h2 = __floats2half2_rn(v1.x, v1.y);
        __half2 h3 = __floats2half2_rn(v1.z, v1.w);
        uint4 o;
        o.x = *(const uint32_t*)&h0;
        o.y = *(const uint32_t*)&h1;
        o.z = *(const uint32_t*)&h2;
        o.w = *(const uint32_t*)&h3;
        *(uint4*)&outp[(size_t)(qrow0 + r) * S_LEN + krow0 + c * 8] = o;

        float s = (v0.x + v0.y) + (v0.z + v0.w) + (v1.x + v1.y) + (v1.z + v1.w);
        s += __shfl_xor_sync(0xFFFFFFFFu, s, 1);
        s += __shfl_xor_sync(0xFFFFFFFFu, s, 2);
        s += __shfl_xor_sync(0xFFFFFFFFu, s, 4);
        s += __shfl_xor_sync(0xFFFFFFFFu, s, 8);
        if ((tid & 15) == 0)
            g_psum[((size_t)h * S_LEN + qrow0 + r) * 16 + blockIdx.x] = s;
    }
}

// ---------------------------------------------------------------------------
// Kernel 3: finalize probs: probs[row][k] = half_e[row][k] / rowsum.
// One block per (head,row). Row reciprocal computed from the 16 psum entries.
// Pure streaming kernel (134 MB read + 268 MB write).
// ---------------------------------------------------------------------------
__global__ __launch_bounds__(256) void finalize_kernel(float* __restrict__ probs)
{
    const size_t row = blockIdx.x;
    const float* p = &g_psum[row * 16];
    float s = 0.0f;
    #pragma unroll
    for (int i = 0; i < 16; i++) s += p[i];
    const float rinv = 1.0f / s;

    const uint4* src = (const uint4*)(g_eh + row * S_LEN);
    float4* dst = (float4*)(probs + row * S_LEN);
    const int tid = threadIdx.x;

    uint4 uv = src[tid];
    __half2 h0 = *(const __half2*)&uv.x;
    __half2 h1 = *(const __half2*)&uv.y;
    __half2 h2 = *(const __half2*)&uv.z;
    __half2 h3 = *(const __half2*)&uv.w;
    float2 f0 = __half22float2(h0);
    float2 f1 = __half22float2(h1);
    float2 f2 = __half22float2(h2);
    float2 f3 = __half22float2(h3);
    dst[2 * tid]     = make_float4(f0.x * rinv, f0.y * rinv, f1.x * rinv, f1.y * rinv);
    dst[2 * tid + 1] = make_float4(f2.x * rinv, f2.y * rinv, f3.x * rinv, f3.y * rinv);
}

// ---------------------------------------------------------------------------
// Kernel 4: PV on unnormalized half e; row scaling applied to output via
// smem stage. Row reciprocals computed in-kernel from g_psum.
// BM=128, BK=64. 8 warps (4x2), warp tile 32x32. grid = (16 qstrips, 16 heads).
// ---------------------------------------------------------------------------
__global__ __launch_bounds__(256) void pv_kernel(float* __restrict__ ctx)
{
    constexpr int BM = 128, BK = 64;
    const int h = blockIdx.y;
    const __half* E  = g_eh + (size_t)h * S_LEN * S_LEN;
    const __half* vp = g_vh + h * HD;

    __shared__ __align__(16) union {
        struct { __half P[BM][BK + 8]; __half V[BK][HD + 8]; } in;
        float C[BM][HD + 4];
    } u;
    __shared__ float rinv[BM];

    const int tid  = threadIdx.x;
    const int warp = tid >> 5;
    const int wm   = warp & 3;
    const int wn   = warp >> 2;
    const int row0 = blockIdx.x * BM;

    if (tid < BM) {
        const float* p = &g_psum[((size_t)h * S_LEN + row0 + tid) * 16];
        float s = 0.0f;
        #pragma unroll
        for (int i = 0; i < 16; i++) s += p[i];
        rinv[tid] = 1.0f / s;
    }

    wmma::fragment<wmma::accumulator, 16, 16, 16, float> acc[2][2];
    #pragma unroll
    for (int i = 0; i < 2; i++)
        #pragma unroll
        for (int j = 0; j < 2; j++)
            wmma::fill_fragment(acc[i][j], 0.0f);

    for (int k0 = 0; k0 < S_LEN; k0 += BK) {
        // P tile: 128 rows x 8 int4 = 1024, 4/thread
        #pragma unroll
        for (int it = 0; it < 4; it++) {
            int idx = tid + it * 256;
            int r = idx >> 3, c = idx & 7;
            *(int4*)&u.in.P[r][c * 8] =
                *(const int4*)&E[(size_t)(row0 + r) * S_LEN + k0 + c * 8];
        }
        // V tile: 64 rows x 8 int4 = 512, 2/thread
        #pragma unroll
        for (int it = 0; it < 2; it++) {
            int idx = tid + it * 256;
            int r = idx >> 3, c = idx & 7;
            *(int4*)&u.in.V[r][c * 8] =
                *(const int4*)&vp[(size_t)(k0 + r) * DM + c * 8];
        }
        __syncthreads();

        #pragma unroll
        for (int kk = 0; kk < BK; kk += 16) {
            wmma::fragment<wmma::matrix_a, 16, 16, 16, __half, wmma::row_major> a[2];
            wmma::fragment<wmma::matrix_b, 16, 16, 16, __half, wmma::row_major> b[2];
            #pragma unroll
            for (int i = 0; i < 2; i++)
                wmma::load_matrix_sync(a[i], &u.in.P[wm * 32 + i * 16][kk], BK + 8);
            #pragma unroll
            for (int j = 0; j < 2; j++)
                wmma::load_matrix_sync(b[j], &u.in.V[kk][wn * 32 + j * 16], HD + 8);
            #pragma unroll
            for (int i = 0; i < 2; i++)
                #pragma unroll
                for (int j = 0; j < 2; j++)
                    wmma::mma_sync(acc[i][j], a[i], b[j], acc[i][j]);
        }
        __syncthreads();
    }

    // Stage, scale rows by rinv, coalesced store.
    #pragma unroll
    for (int i = 0; i < 2; i++)
        #pragma unroll
        for (int j = 0; j < 2; j++)
            wmma::store_matrix_sync(&u.C[wm * 32 + i * 16][wn * 32 + j * 16],
                                    acc[i][j], HD + 4, wmma::mem_row_major);
    __syncthreads();

    #pragma unroll
    for (int it = 0; it < 8; it++) {
        int idx = tid + it * 256;        // 128 rows x 16 float4
        int r = idx >> 4, c4 = idx & 15;
        float iv = rinv[r];
        float4 v = *(const float4*)&u.C[r][c4 * 4];
        v.x *= iv; v.y *= iv; v.z *= iv; v.w *= iv;
        *(float4*)&ctx[(size_t)(row0 + r) * DM + h * HD + c4 * 4] = v;
    }
}

// ---------------------------------------------------------------------------
// Launch. d_out layout: context (2048*1024 floats) then probs (16*2048*2048).
// ---------------------------------------------------------------------------
extern "C" void kernel_launch(void* const* d_in, const int* in_sizes, int n_in,
                              void* d_out, int out_size)
{
    const float* hs = (const float*)d_in[0];
    const float* Wq = (const float*)d_in[1];
    const float* Wk = (const float*)d_in[2];
    const float* Wv = (const float*)d_in[3];

    float* ctx   = (float*)d_out;
    float* probs = ctx + (size_t)S_LEN * DM;

    cvt_x_kernel<<<dim3(S_LEN * DM / 4 / 256), 256>>>(hs);
    cvt_w_kernel<<<dim3(DM * DM / 4 / 256, 1, 3), 256>>>(Wq, Wk, Wv);
    qkv_gemm_kernel<<<dim3(DM / 64, S_LEN / 128, 3), 256>>>();
    scores_exp_kernel<<<dim3(S_LEN / 128, S_LEN / 128, NH), 256>>>();
    pv_kernel<<<dim3(S_LEN / 128, NH), 256>>>(ctx);
    finalize_kernel<<<dim3(NH * S_LEN), 256>>>(probs);
}

// round 10
// speedup vs baseline: 1.1090x; 1.1090x over previous
#include <cuda_runtime.h>
#include <cuda_fp16.h>
#include <mma.h>
#include <math.h>
#include <cstdint>

using namespace nvcuda;

#define S_LEN 2048
#define DM    1024
#define NH    16
#define HD    64

// Scratch (allocation-guard rules: __device__ globals).
__device__ __half g_xh[S_LEN * DM];
__device__ __half g_wh[3][DM * DM];
__device__ __half g_qh[S_LEN * DM];
__device__ __half g_kh[S_LEN * DM];
__device__ __half g_vh[S_LEN * DM];
__device__ __half g_eh[(size_t)NH * S_LEN * S_LEN];  // unnormalized exp(scores), half
__device__ float  g_psum[NH * S_LEN * 16];           // per-(row, ktile) partial sums
__device__ float  g_rinv[NH * S_LEN];                // 1 / rowsum

// ---------------------------------------------------------------------------
// fp32 -> fp16 converters.
// ---------------------------------------------------------------------------
__device__ __forceinline__ void cvt4(const float* __restrict__ src,
                                     __half* __restrict__ dst, size_t i)
{
    float4 v = ((const float4*)src)[i];
    __half2 a = __floats2half2_rn(v.x, v.y);
    __half2 b = __floats2half2_rn(v.z, v.w);
    uint2 u;
    u.x = *(const uint32_t*)&a;
    u.y = *(const uint32_t*)&b;
    ((uint2*)dst)[i] = u;
}

__global__ __launch_bounds__(256) void cvt_x_kernel(const float* __restrict__ X)
{
    cvt4(X, g_xh, (size_t)blockIdx.x * 256 + threadIdx.x);
}

__global__ __launch_bounds__(256) void cvt_w_kernel(
    const float* __restrict__ Wq, const float* __restrict__ Wk,
    const float* __restrict__ Wv)
{
    const float* src = (blockIdx.z == 0) ? Wq : (blockIdx.z == 1) ? Wk : Wv;
    cvt4(src, g_wh[blockIdx.z], (size_t)blockIdx.x * 256 + threadIdx.x);
}

// ---------------------------------------------------------------------------
// Kernel 1: QKV projection, fp16 in / fp32 accum / fp16 out.
// BM=128, BN=64, BK=32. 8 warps (4x2), warp tile 32x32.
// C-stage unioned with input tiles: smem 50 -> 35 KB (6 blocks/SM).
// ---------------------------------------------------------------------------
__global__ __launch_bounds__(256) void qkv_gemm_kernel()
{
    constexpr int BM = 128, BN = 64, BK = 32;
    const __half* W = g_wh[blockIdx.z];
    __half*       Y = (blockIdx.z == 0) ? g_qh : (blockIdx.z == 1) ? g_kh : g_vh;

    __shared__ __align__(16) union {
        struct { __half A[BM][BK + 8]; __half B[BK][BN + 8]; } in;
        float C[BM][BN + 4];
    } u;

    const int tid  = threadIdx.x;
    const int warp = tid >> 5;
    const int wm   = warp & 3;
    const int wn   = warp >> 2;

    const int row0 = blockIdx.y * BM;
    const int col0 = blockIdx.x * BN;

    wmma::fragment<wmma::accumulator, 16, 16, 16, float> acc[2][2];
    #pragma unroll
    for (int i = 0; i < 2; i++)
        #pragma unroll
        for (int j = 0; j < 2; j++)
            wmma::fill_fragment(acc[i][j], 0.0f);

    for (int k0 = 0; k0 < DM; k0 += BK) {
        #pragma unroll
        for (int it = 0; it < 2; it++) {
            int idx = tid + it * 256;
            int r = idx >> 2, c = idx & 3;
            *(int4*)&u.in.A[r][c * 8] =
                *(const int4*)&g_xh[(size_t)(row0 + r) * DM + k0 + c * 8];
        }
        {
            int r = tid >> 3, c = tid & 7;
            *(int4*)&u.in.B[r][c * 8] =
                *(const int4*)&W[(size_t)(k0 + r) * DM + col0 + c * 8];
        }
        __syncthreads();

        #pragma unroll
        for (int kk = 0; kk < BK; kk += 16) {
            wmma::fragment<wmma::matrix_a, 16, 16, 16, __half, wmma::row_major> a[2];
            wmma::fragment<wmma::matrix_b, 16, 16, 16, __half, wmma::row_major> b[2];
            #pragma unroll
            for (int i = 0; i < 2; i++)
                wmma::load_matrix_sync(a[i], &u.in.A[wm * 32 + i * 16][kk], BK + 8);
            #pragma unroll
            for (int j = 0; j < 2; j++)
                wmma::load_matrix_sync(b[j], &u.in.B[kk][wn * 32 + j * 16], BN + 8);
            #pragma unroll
            for (int i = 0; i < 2; i++)
                #pragma unroll
                for (int j = 0; j < 2; j++)
                    wmma::mma_sync(acc[i][j], a[i], b[j], acc[i][j]);
        }
        __syncthreads();
    }

    #pragma unroll
    for (int i = 0; i < 2; i++)
        #pragma unroll
        for (int j = 0; j < 2; j++)
            wmma::store_matrix_sync(&u.C[wm * 32 + i * 16][wn * 32 + j * 16],
                                    acc[i][j], BN + 4, wmma::mem_row_major);
    __syncthreads();

    #pragma unroll
    for (int it = 0; it < 8; it++) {
        int idx = tid + it * 256;
        int r = idx >> 4, c4 = idx & 15;
        float4 v = *(const float4*)&u.C[r][c4 * 4];
        __half2 h0 = __floats2half2_rn(v.x, v.y);
        __half2 h1 = __floats2half2_rn(v.z, v.w);
        uint2 o;
        o.x = *(const uint32_t*)&h0;
        o.y = *(const uint32_t*)&h1;
        *(uint2*)&Y[(size_t)(row0 + r) * DM + col0 + c4 * 4] = o;
    }
}

// ---------------------------------------------------------------------------
// Kernel 2: e = exp(q.k/8) (unnormalized), written as HALF to g_eh.
// 128x128 tile, 8 warps (4x2), warp tile 32x64. exp applied in registers.
// fp32 stage split into two 64-col passes: smem 68 -> 37 KB (6 blocks/SM).
// Chunk sums accumulate in registers across passes; one psum write per row.
// ---------------------------------------------------------------------------
__global__ __launch_bounds__(256) void scores_exp_kernel()
{
    const int h = blockIdx.z;
    __shared__ __align__(16) union {
        struct { __half Q[128][HD + 8]; __half K[128][HD + 8]; } in;
        float S[128][68];   // 64-col stage (+4 pad)
    } u;

    const int tid  = threadIdx.x;
    const int warp = tid >> 5;
    const int wm   = warp & 3;   // 4 strips of 32 q-rows
    const int wn   = warp >> 2;  // 2 strips of 64 k-cols

    const int qrow0 = blockIdx.y * 128;
    const int krow0 = blockIdx.x * 128;
    const __half* qp = g_qh + h * HD;
    const __half* kp = g_kh + h * HD;

    #pragma unroll
    for (int it = 0; it < 4; it++) {
        int idx = tid + it * 256;
        int r = idx >> 3, c = idx & 7;
        *(int4*)&u.in.Q[r][c * 8] =
            *(const int4*)&qp[(size_t)(qrow0 + r) * DM + c * 8];
        *(int4*)&u.in.K[r][c * 8] =
            *(const int4*)&kp[(size_t)(krow0 + r) * DM + c * 8];
    }
    __syncthreads();

    wmma::fragment<wmma::accumulator, 16, 16, 16, float> acc[2][4];
    #pragma unroll
    for (int i = 0; i < 2; i++)
        #pragma unroll
        for (int j = 0; j < 4; j++)
            wmma::fill_fragment(acc[i][j], 0.0f);

    #pragma unroll
    for (int kk = 0; kk < HD; kk += 16) {
        wmma::fragment<wmma::matrix_a, 16, 16, 16, __half, wmma::row_major> a[2];
        wmma::fragment<wmma::matrix_b, 16, 16, 16, __half, wmma::col_major> b[4];
        #pragma unroll
        for (int i = 0; i < 2; i++)
            wmma::load_matrix_sync(a[i], &u.in.Q[wm * 32 + i * 16][kk], HD + 8);
        #pragma unroll
        for (int j = 0; j < 4; j++)
            wmma::load_matrix_sync(b[j], &u.in.K[wn * 64 + j * 16][kk], HD + 8);
        #pragma unroll
        for (int i = 0; i < 2; i++)
            #pragma unroll
            for (int j = 0; j < 4; j++)
                wmma::mma_sync(acc[i][j], a[i], b[j], acc[i][j]);
    }

    // exp in registers (all fragments).
    #pragma unroll
    for (int i = 0; i < 2; i++)
        #pragma unroll
        for (int j = 0; j < 4; j++)
            #pragma unroll
            for (int e = 0; e < acc[i][j].num_elements; e++)
                acc[i][j].x[e] = __expf(acc[i][j].x[e] * 0.125f);

    // Two 64-col stage passes. Warps with wn==p own the columns of pass p.
    __half* outp = g_eh + (size_t)h * S_LEN * S_LEN;
    float s_acc[4] = {0.0f, 0.0f, 0.0f, 0.0f};

    #pragma unroll
    for (int p = 0; p < 2; p++) {
        __syncthreads();    // stage (or Q/K tiles) free for rewrite
        if (wn == p) {
            #pragma unroll
            for (int i = 0; i < 2; i++)
                #pragma unroll
                for (int j = 0; j < 4; j++)
                    wmma::store_matrix_sync(&u.S[wm * 32 + i * 16][j * 16],
                                            acc[i][j], 68, wmma::mem_row_major);
        }
        __syncthreads();

        // 128 rows x 8 chunks of 8 floats = 1024 chunks, 4 iters.
        #pragma unroll
        for (int it = 0; it < 4; it++) {
            int idx = tid + it * 256;
            int r = idx >> 3, c = idx & 7;
            float4 v0 = *(const float4*)&u.S[r][c * 8];
            float4 v1 = *(const float4*)&u.S[r][c * 8 + 4];
            __half2 h0 = __floats2half2_rn(v0.x, v0.y);
            __half2 h1 = __floats2half2_rn(v0.z, v0.w);
            __half2 h2 = __floats2half2_rn(v1.x, v1.y);
            __half2 h3 = __floats2half2_rn(v1.z, v1.w);
            uint4 o;
            o.x = *(const uint32_t*)&h0;
            o.y = *(const uint32_t*)&h1;
            o.z = *(const uint32_t*)&h2;
            o.w = *(const uint32_t*)&h3;
            *(uint4*)&outp[(size_t)(qrow0 + r) * S_LEN + krow0 + p * 64 + c * 8] = o;
            s_acc[it] += (v0.x + v0.y) + (v0.z + v0.w) + (v1.x + v1.y) + (v1.z + v1.w);
        }
    }

    // Row sums: 8 threads share a row per iteration; reduce and write once.
    #pragma unroll
    for (int it = 0; it < 4; it++) {
        int idx = tid + it * 256;
        int r = idx >> 3;
        float s = s_acc[it];
        s += __shfl_xor_sync(0xFFFFFFFFu, s, 1);
        s += __shfl_xor_sync(0xFFFFFFFFu, s, 2);
        s += __shfl_xor_sync(0xFFFFFFFFu, s, 4);
        if ((tid & 7) == 0)
            g_psum[((size_t)h * S_LEN + qrow0 + r) * 16 + blockIdx.x] = s;
    }
}

// ---------------------------------------------------------------------------
// Kernel 3: rowsum -> reciprocal. One thread per (head, row). Deterministic.
// ---------------------------------------------------------------------------
__global__ __launch_bounds__(256) void rowsum_kernel()
{
    int row = blockIdx.x * 256 + threadIdx.x;
    const float* p = &g_psum[(size_t)row * 16];
    float s = 0.0f;
    #pragma unroll
    for (int i = 0; i < 16; i++) s += p[i];
    g_rinv[row] = 1.0f / s;
}

// ---------------------------------------------------------------------------
// Kernel 4: finalize probs: probs[row][k] = half_e[row][k] * rinv[row].
// One block per (head,row). Pure streaming (134 MB read + 268 MB write).
// ---------------------------------------------------------------------------
__global__ __launch_bounds__(256) void finalize_kernel(float* __restrict__ probs)
{
    const size_t row = blockIdx.x;
    const float rinv = g_rinv[row];
    const uint4* src = (const uint4*)(g_eh + row * S_LEN);
    float4* dst = (float4*)(probs + row * S_LEN);
    const int tid = threadIdx.x;

    uint4 uv = src[tid];
    __half2 h0 = *(const __half2*)&uv.x;
    __half2 h1 = *(const __half2*)&uv.y;
    __half2 h2 = *(const __half2*)&uv.z;
    __half2 h3 = *(const __half2*)&uv.w;
    float2 f0 = __half22float2(h0);
    float2 f1 = __half22float2(h1);
    float2 f2 = __half22float2(h2);
    float2 f3 = __half22float2(h3);
    dst[2 * tid]     = make_float4(f0.x * rinv, f0.y * rinv, f1.x * rinv, f1.y * rinv);
    dst[2 * tid + 1] = make_float4(f2.x * rinv, f2.y * rinv, f3.x * rinv, f3.y * rinv);
}

// ---------------------------------------------------------------------------
// Kernel 5: PV on unnormalized half e; row scaling by rinv applied to the
// output through an smem stage. BM=128, BK=64. 8 warps (4x2), warp tile 32x32.
// ---------------------------------------------------------------------------
__global__ __launch_bounds__(256) void pv_kernel(float* __restrict__ ctx)
{
    constexpr int BM = 128, BK = 64;
    const int h = blockIdx.y;
    const __half* E  = g_eh + (size_t)h * S_LEN * S_LEN;
    const __half* vp = g_vh + h * HD;

    __shared__ __align__(16) union {
        struct { __half P[BM][BK + 8]; __half V[BK][HD + 8]; } in;
        float C[BM][HD + 4];
    } u;
    __shared__ float rinv[BM];

    const int tid  = threadIdx.x;
    const int warp = tid >> 5;
    const int wm   = warp & 3;
    const int wn   = warp >> 2;
    const int row0 = blockIdx.x * BM;

    if (tid < BM)
        rinv[tid] = g_rinv[(size_t)h * S_LEN + row0 + tid];

    wmma::fragment<wmma::accumulator, 16, 16, 16, float> acc[2][2];
    #pragma unroll
    for (int i = 0; i < 2; i++)
        #pragma unroll
        for (int j = 0; j < 2; j++)
            wmma::fill_fragment(acc[i][j], 0.0f);

    for (int k0 = 0; k0 < S_LEN; k0 += BK) {
        // P tile: 128 rows x 8 int4 = 1024, 4/thread
        #pragma unroll
        for (int it = 0; it < 4; it++) {
            int idx = tid + it * 256;
            int r = idx >> 3, c = idx & 7;
            *(int4*)&u.in.P[r][c * 8] =
                *(const int4*)&E[(size_t)(row0 + r) * S_LEN + k0 + c * 8];
        }
        // V tile: 64 rows x 8 int4 = 512, 2/thread
        #pragma unroll
        for (int it = 0; it < 2; it++) {
            int idx = tid + it * 256;
            int r = idx >> 3, c = idx & 7;
            *(int4*)&u.in.V[r][c * 8] =
                *(const int4*)&vp[(size_t)(k0 + r) * DM + c * 8];
        }
        __syncthreads();

        #pragma unroll
        for (int kk = 0; kk < BK; kk += 16) {
            wmma::fragment<wmma::matrix_a, 16, 16, 16, __half, wmma::row_major> a[2];
            wmma::fragment<wmma::matrix_b, 16, 16, 16, __half, wmma::row_major> b[2];
            #pragma unroll
            for (int i = 0; i < 2; i++)
                wmma::load_matrix_sync(a[i], &u.in.P[wm * 32 + i * 16][kk], BK + 8);
            #pragma unroll
            for (int j = 0; j < 2; j++)
                wmma::load_matrix_sync(b[j], &u.in.V[kk][wn * 32 + j * 16], HD + 8);
            #pragma unroll
            for (int i = 0; i < 2; i++)
                #pragma unroll
                for (int j = 0; j < 2; j++)
                    wmma::mma_sync(acc[i][j], a[i], b[j], acc[i][j]);
        }
        __syncthreads();
    }

    // Stage, scale rows by rinv, coalesced store.
    #pragma unroll
    for (int i = 0; i < 2; i++)
        #pragma unroll
        for (int j = 0; j < 2; j++)
            wmma::store_matrix_sync(&u.C[wm * 32 + i * 16][wn * 32 + j * 16],
                                    acc[i][j], HD + 4, wmma::mem_row_major);
    __syncthreads();

    #pragma unroll
    for (int it = 0; it < 8; it++) {
        int idx = tid + it * 256;        // 128 rows x 16 float4
        int r = idx >> 4, c4 = idx & 15;
        float iv = rinv[r];
        float4 v = *(const float4*)&u.C[r][c4 * 4];
        v.x *= iv; v.y *= iv; v.z *= iv; v.w *= iv;
        *(float4*)&ctx[(size_t)(row0 + r) * DM + h * HD + c4 * 4] = v;
    }
}

// ---------------------------------------------------------------------------
// Launch. d_out layout: context (2048*1024 floats) then probs (16*2048*2048).
// ---------------------------------------------------------------------------
extern "C" void kernel_launch(void* const* d_in, const int* in_sizes, int n_in,
                              void* d_out, int out_size)
{
    const float* hs = (const float*)d_in[0];
    const float* Wq = (const float*)d_in[1];
    const float* Wk = (const float*)d_in[2];
    const float* Wv = (const float*)d_in[3];

    float* ctx   = (float*)d_out;
    float* probs = ctx + (size_t)S_LEN * DM;

    cvt_x_kernel<<<dim3(S_LEN * DM / 4 / 256), 256>>>(hs);
    cvt_w_kernel<<<dim3(DM * DM / 4 / 256, 1, 3), 256>>>(Wq, Wk, Wv);
    qkv_gemm_kernel<<<dim3(DM / 64, S_LEN / 128, 3), 256>>>();
    scores_exp_kernel<<<dim3(S_LEN / 128, S_LEN / 128, NH), 256>>>();
    rowsum_kernel<<<dim3(NH * S_LEN / 256), 256>>>();
    pv_kernel<<<dim3(S_LEN / 128, NH), 256>>>(ctx);
    finalize_kernel<<<dim3(NH * S_LEN), 256>>>(probs);
}

// round 11
// speedup vs baseline: 1.1444x; 1.0319x over previous
#include <cuda_runtime.h>
#include <cuda_fp16.h>
#include <mma.h>
#include <math.h>
#include <cstdint>

using namespace nvcuda;

#define S_LEN 2048
#define DM    1024
#define NH    16
#define HD    64

// Scratch (allocation-guard rules: __device__ globals).
__device__ __half g_xh[S_LEN * DM];
__device__ __half g_wh[3][DM * DM];
__device__ __half g_qh[S_LEN * DM];
__device__ __half g_kh[S_LEN * DM];
__device__ __half g_vh[S_LEN * DM];
__device__ __half g_eh[(size_t)NH * S_LEN * S_LEN];  // unnormalized exp(scores), half
__device__ float  g_psum[(size_t)NH * S_LEN * 32];   // per-(row, ktile, wn) partials
__device__ float  g_rinv[NH * S_LEN];                // 1 / rowsum

// ---------------------------------------------------------------------------
// fp32 -> fp16 converters.
// ---------------------------------------------------------------------------
__device__ __forceinline__ void cvt4(const float* __restrict__ src,
                                     __half* __restrict__ dst, size_t i)
{
    float4 v = ((const float4*)src)[i];
    __half2 a = __floats2half2_rn(v.x, v.y);
    __half2 b = __floats2half2_rn(v.z, v.w);
    uint2 u;
    u.x = *(const uint32_t*)&a;
    u.y = *(const uint32_t*)&b;
    ((uint2*)dst)[i] = u;
}

__global__ __launch_bounds__(256) void cvt_x_kernel(const float* __restrict__ X)
{
    cvt4(X, g_xh, (size_t)blockIdx.x * 256 + threadIdx.x);
}

__global__ __launch_bounds__(256) void cvt_w_kernel(
    const float* __restrict__ Wq, const float* __restrict__ Wk,
    const float* __restrict__ Wv)
{
    const float* src = (blockIdx.z == 0) ? Wq : (blockIdx.z == 1) ? Wk : Wv;
    cvt4(src, g_wh[blockIdx.z], (size_t)blockIdx.x * 256 + threadIdx.x);
}

// ---------------------------------------------------------------------------
// Kernel 1: QKV projection (unchanged from round 10).
// ---------------------------------------------------------------------------
__global__ __launch_bounds__(256) void qkv_gemm_kernel()
{
    constexpr int BM = 128, BN = 64, BK = 32;
    const __half* W = g_wh[blockIdx.z];
    __half*       Y = (blockIdx.z == 0) ? g_qh : (blockIdx.z == 1) ? g_kh : g_vh;

    __shared__ __align__(16) union {
        struct { __half A[BM][BK + 8]; __half B[BK][BN + 8]; } in;
        float C[BM][BN + 4];
    } u;

    const int tid  = threadIdx.x;
    const int warp = tid >> 5;
    const int wm   = warp & 3;
    const int wn   = warp >> 2;

    const int row0 = blockIdx.y * BM;
    const int col0 = blockIdx.x * BN;

    wmma::fragment<wmma::accumulator, 16, 16, 16, float> acc[2][2];
    #pragma unroll
    for (int i = 0; i < 2; i++)
        #pragma unroll
        for (int j = 0; j < 2; j++)
            wmma::fill_fragment(acc[i][j], 0.0f);

    for (int k0 = 0; k0 < DM; k0 += BK) {
        #pragma unroll
        for (int it = 0; it < 2; it++) {
            int idx = tid + it * 256;
            int r = idx >> 2, c = idx & 3;
            *(int4*)&u.in.A[r][c * 8] =
                *(const int4*)&g_xh[(size_t)(row0 + r) * DM + k0 + c * 8];
        }
        {
            int r = tid >> 3, c = tid & 7;
            *(int4*)&u.in.B[r][c * 8] =
                *(const int4*)&W[(size_t)(k0 + r) * DM + col0 + c * 8];
        }
        __syncthreads();

        #pragma unroll
        for (int kk = 0; kk < BK; kk += 16) {
            wmma::fragment<wmma::matrix_a, 16, 16, 16, __half, wmma::row_major> a[2];
            wmma::fragment<wmma::matrix_b, 16, 16, 16, __half, wmma::row_major> b[2];
            #pragma unroll
            for (int i = 0; i < 2; i++)
                wmma::load_matrix_sync(a[i], &u.in.A[wm * 32 + i * 16][kk], BK + 8);
            #pragma unroll
            for (int j = 0; j < 2; j++)
                wmma::load_matrix_sync(b[j], &u.in.B[kk][wn * 32 + j * 16], BN + 8);
            #pragma unroll
            for (int i = 0; i < 2; i++)
                #pragma unroll
                for (int j = 0; j < 2; j++)
                    wmma::mma_sync(acc[i][j], a[i], b[j], acc[i][j]);
        }
        __syncthreads();
    }

    #pragma unroll
    for (int i = 0; i < 2; i++)
        #pragma unroll
        for (int j = 0; j < 2; j++)
            wmma::store_matrix_sync(&u.C[wm * 32 + i * 16][wn * 32 + j * 16],
                                    acc[i][j], BN + 4, wmma::mem_row_major);
    __syncthreads();

    #pragma unroll
    for (int it = 0; it < 8; it++) {
        int idx = tid + it * 256;
        int r = idx >> 4, c4 = idx & 15;
        float4 v = *(const float4*)&u.C[r][c4 * 4];
        __half2 h0 = __floats2half2_rn(v.x, v.y);
        __half2 h1 = __floats2half2_rn(v.z, v.w);
        uint2 o;
        o.x = *(const uint32_t*)&h0;
        o.y = *(const uint32_t*)&h1;
        *(uint2*)&Y[(size_t)(row0 + r) * DM + col0 + c4 * 4] = o;
    }
}

// ---------------------------------------------------------------------------
// Kernel 2: e = exp(q.k/8), raw mma.sync.m16n8k16 + ldmatrix.
// 128x128 tile, 8 warps (4 m-strips x 2 n-strips), warp tile 32x64.
// exp + row sums computed on accumulator registers (documented layout);
// half output staged once (32KB) then coalesced to gmem.
// ---------------------------------------------------------------------------
__global__ __launch_bounds__(256) void scores_exp_kernel()
{
    const int h = blockIdx.z;
    __shared__ __align__(16) union {
        struct { __half Q[128][72]; __half K[128][72]; } in;   // 36.9 KB
        __half E[128][136];                                    // 34.8 KB
    } u;

    const int tid  = threadIdx.x;
    const int warp = tid >> 5;
    const int lane = tid & 31;
    const int wm   = warp & 3;   // 4 strips of 32 q-rows
    const int wn   = warp >> 2;  // 2 strips of 64 k-cols

    const int qrow0 = blockIdx.y * 128;
    const int krow0 = blockIdx.x * 128;
    const __half* qp = g_qh + h * HD;
    const __half* kp = g_kh + h * HD;

    #pragma unroll
    for (int it = 0; it < 4; it++) {
        int idx = tid + it * 256;
        int r = idx >> 3, c = idx & 7;
        *(int4*)&u.in.Q[r][c * 8] =
            *(const int4*)&qp[(size_t)(qrow0 + r) * DM + c * 8];
        *(int4*)&u.in.K[r][c * 8] =
            *(const int4*)&kp[(size_t)(krow0 + r) * DM + c * 8];
    }
    __syncthreads();

    float c[2][8][4];
    #pragma unroll
    for (int mi = 0; mi < 2; mi++)
        #pragma unroll
        for (int ni = 0; ni < 8; ni++)
            #pragma unroll
            for (int e = 0; e < 4; e++)
                c[mi][ni][e] = 0.0f;

    const uint32_t qs = (uint32_t)__cvta_generic_to_shared(&u.in.Q[0][0]);
    const uint32_t ks = (uint32_t)__cvta_generic_to_shared(&u.in.K[0][0]);
    const int lrow = lane & 15;
    const int lk   = (lane >> 4) * 8;

    #pragma unroll
    for (int kk = 0; kk < HD; kk += 16) {
        uint32_t a[2][4];
        #pragma unroll
        for (int mi = 0; mi < 2; mi++) {
            uint32_t addr = qs + (uint32_t)(((wm * 32 + mi * 16 + lrow) * 72 + kk + lk) * 2);
            asm volatile(
                "ldmatrix.sync.aligned.m8n8.x4.shared.b16 {%0,%1,%2,%3}, [%4];"
                : "=r"(a[mi][0]), "=r"(a[mi][1]), "=r"(a[mi][2]), "=r"(a[mi][3])
                : "r"(addr));
        }
        #pragma unroll
        for (int nb = 0; nb < 4; nb++) {
            uint32_t b0, b1, b2, b3;
            uint32_t addr = ks + (uint32_t)(((wn * 64 + nb * 16 + lrow) * 72 + kk + lk) * 2);
            asm volatile(
                "ldmatrix.sync.aligned.m8n8.x4.shared.b16 {%0,%1,%2,%3}, [%4];"
                : "=r"(b0), "=r"(b1), "=r"(b2), "=r"(b3)
                : "r"(addr));
            #pragma unroll
            for (int mi = 0; mi < 2; mi++) {
                asm volatile(
                    "mma.sync.aligned.m16n8k16.row.col.f32.f16.f16.f32 "
                    "{%0,%1,%2,%3}, {%4,%5,%6,%7}, {%8,%9}, {%0,%1,%2,%3};"
                    : "+f"(c[mi][2 * nb][0]), "+f"(c[mi][2 * nb][1]),
                      "+f"(c[mi][2 * nb][2]), "+f"(c[mi][2 * nb][3])
                    : "r"(a[mi][0]), "r"(a[mi][1]), "r"(a[mi][2]), "r"(a[mi][3]),
                      "r"(b0), "r"(b2));
                asm volatile(
                    "mma.sync.aligned.m16n8k16.row.col.f32.f16.f16.f32 "
                    "{%0,%1,%2,%3}, {%4,%5,%6,%7}, {%8,%9}, {%0,%1,%2,%3};"
                    : "+f"(c[mi][2 * nb + 1][0]), "+f"(c[mi][2 * nb + 1][1]),
                      "+f"(c[mi][2 * nb + 1][2]), "+f"(c[mi][2 * nb + 1][3])
                    : "r"(a[mi][0]), "r"(a[mi][1]), "r"(a[mi][2]), "r"(a[mi][3]),
                      "r"(b1), "r"(b3));
            }
        }
    }
    __syncthreads();   // Q/K dead; union stage may be written

    // exp in registers + per-row sums (4-lane groups share a row).
    #pragma unroll
    for (int mi = 0; mi < 2; mi++) {
        float sA = 0.0f, sB = 0.0f;
        #pragma unroll
        for (int ni = 0; ni < 8; ni++) {
            #pragma unroll
            for (int e = 0; e < 4; e++)
                c[mi][ni][e] = __expf(c[mi][ni][e] * 0.125f);
            sA += c[mi][ni][0] + c[mi][ni][1];
            sB += c[mi][ni][2] + c[mi][ni][3];
        }
        sA += __shfl_xor_sync(0xFFFFFFFFu, sA, 1);
        sA += __shfl_xor_sync(0xFFFFFFFFu, sA, 2);
        sB += __shfl_xor_sync(0xFFFFFFFFu, sB, 1);
        sB += __shfl_xor_sync(0xFFFFFFFFu, sB, 2);
        if ((lane & 3) == 0) {
            int r = wm * 32 + mi * 16 + (lane >> 2);
            g_psum[((size_t)h * S_LEN + qrow0 + r) * 32 + blockIdx.x * 2 + wn] = sA;
            g_psum[((size_t)h * S_LEN + qrow0 + r + 8) * 32 + blockIdx.x * 2 + wn] = sB;
        }
    }

    // Stage half output (known accumulator layout: row lane/4 (+8), col 2*(lane%4)).
    #pragma unroll
    for (int mi = 0; mi < 2; mi++)
        #pragma unroll
        for (int ni = 0; ni < 8; ni++) {
            int r   = wm * 32 + mi * 16 + (lane >> 2);
            int col = wn * 64 + ni * 8 + 2 * (lane & 3);
            __half2 lo = __floats2half2_rn(c[mi][ni][0], c[mi][ni][1]);
            __half2 hi = __floats2half2_rn(c[mi][ni][2], c[mi][ni][3]);
            *(__half2*)&u.E[r][col]     = lo;
            *(__half2*)&u.E[r + 8][col] = hi;
        }
    __syncthreads();

    // Coalesced write of the half e-tile.
    __half* outp = g_eh + (size_t)h * S_LEN * S_LEN;
    #pragma unroll
    for (int it = 0; it < 8; it++) {
        int idx = tid + it * 256;
        int r = idx >> 4, cc = idx & 15;
        uint4 o = *(const uint4*)&u.E[r][cc * 8];
        *(uint4*)&outp[(size_t)(qrow0 + r) * S_LEN + krow0 + cc * 8] = o;
    }
}

// ---------------------------------------------------------------------------
// Kernel 3: rowsum -> reciprocal. One thread per (head, row).
// ---------------------------------------------------------------------------
__global__ __launch_bounds__(256) void rowsum_kernel()
{
    int row = blockIdx.x * 256 + threadIdx.x;
    const float* p = &g_psum[(size_t)row * 32];
    float s = 0.0f;
    #pragma unroll
    for (int i = 0; i < 32; i++) s += p[i];
    g_rinv[row] = 1.0f / s;
}

// ---------------------------------------------------------------------------
// Kernel 4: finalize probs with streaming (__stwt) stores.
// ---------------------------------------------------------------------------
__global__ __launch_bounds__(256) void finalize_kernel(float* __restrict__ probs)
{
    const size_t row = blockIdx.x;
    const float rinv = g_rinv[row];
    const uint4* src = (const uint4*)(g_eh + row * S_LEN);
    float4* dst = (float4*)(probs + row * S_LEN);
    const int tid = threadIdx.x;

    uint4 uv = src[tid];
    __half2 h0 = *(const __half2*)&uv.x;
    __half2 h1 = *(const __half2*)&uv.y;
    __half2 h2 = *(const __half2*)&uv.z;
    __half2 h3 = *(const __half2*)&uv.w;
    float2 f0 = __half22float2(h0);
    float2 f1 = __half22float2(h1);
    float2 f2 = __half22float2(h2);
    float2 f3 = __half22float2(h3);
    __stwt(&dst[2 * tid],
           make_float4(f0.x * rinv, f0.y * rinv, f1.x * rinv, f1.y * rinv));
    __stwt(&dst[2 * tid + 1],
           make_float4(f2.x * rinv, f2.y * rinv, f3.x * rinv, f3.y * rinv));
}

// ---------------------------------------------------------------------------
// Kernel 5: PV on unnormalized half e (unchanged from round 10).
// ---------------------------------------------------------------------------
__global__ __launch_bounds__(256) void pv_kernel(float* __restrict__ ctx)
{
    constexpr int BM = 128, BK = 64;
    const int h = blockIdx.y;
    const __half* E  = g_eh + (size_t)h * S_LEN * S_LEN;
    const __half* vp = g_vh + h * HD;

    __shared__ __align__(16) union {
        struct { __half P[BM][BK + 8]; __half V[BK][HD + 8]; } in;
        float C[BM][HD + 4];
    } u;
    __shared__ float rinv[BM];

    const int tid  = threadIdx.x;
    const int warp = tid >> 5;
    const int wm   = warp & 3;
    const int wn   = warp >> 2;
    const int row0 = blockIdx.x * BM;

    if (tid < BM)
        rinv[tid] = g_rinv[(size_t)h * S_LEN + row0 + tid];

    wmma::fragment<wmma::accumulator, 16, 16, 16, float> acc[2][2];
    #pragma unroll
    for (int i = 0; i < 2; i++)
        #pragma unroll
        for (int j = 0; j < 2; j++)
            wmma::fill_fragment(acc[i][j], 0.0f);

    for (int k0 = 0; k0 < S_LEN; k0 += BK) {
        #pragma unroll
        for (int it = 0; it < 4; it++) {
            int idx = tid + it * 256;
            int r = idx >> 3, c = idx & 7;
            *(int4*)&u.in.P[r][c * 8] =
                *(const int4*)&E[(size_t)(row0 + r) * S_LEN + k0 + c * 8];
        }
        #pragma unroll
        for (int it = 0; it < 2; it++) {
            int idx = tid + it * 256;
            int r = idx >> 3, c = idx & 7;
            *(int4*)&u.in.V[r][c * 8] =
                *(const int4*)&vp[(size_t)(k0 + r) * DM + c * 8];
        }
        __syncthreads();

        #pragma unroll
        for (int kk = 0; kk < BK; kk += 16) {
            wmma::fragment<wmma::matrix_a, 16, 16, 16, __half, wmma::row_major> a[2];
            wmma::fragment<wmma::matrix_b, 16, 16, 16, __half, wmma::row_major> b[2];
            #pragma unroll
            for (int i = 0; i < 2; i++)
                wmma::load_matrix_sync(a[i], &u.in.P[wm * 32 + i * 16][kk], BK + 8);
            #pragma unroll
            for (int j = 0; j < 2; j++)
                wmma::load_matrix_sync(b[j], &u.in.V[kk][wn * 32 + j * 16], HD + 8);
            #pragma unroll
            for (int i = 0; i < 2; i++)
                #pragma unroll
                for (int j = 0; j < 2; j++)
                    wmma::mma_sync(acc[i][j], a[i], b[j], acc[i][j]);
        }
        __syncthreads();
    }

    #pragma unroll
    for (int i = 0; i < 2; i++)
        #pragma unroll
        for (int j = 0; j < 2; j++)
            wmma::store_matrix_sync(&u.C[wm * 32 + i * 16][wn * 32 + j * 16],
                                    acc[i][j], HD + 4, wmma::mem_row_major);
    __syncthreads();

    #pragma unroll
    for (int it = 0; it < 8; it++) {
        int idx = tid + it * 256;
        int r = idx >> 4, c4 = idx & 15;
        float iv = rinv[r];
        float4 v = *(const float4*)&u.C[r][c4 * 4];
        v.x *= iv; v.y *= iv; v.z *= iv; v.w *= iv;
        *(float4*)&ctx[(size_t)(row0 + r) * DM + h * HD + c4 * 4] = v;
    }
}

// ---------------------------------------------------------------------------
// Launch. d_out layout: context (2048*1024 floats) then probs (16*2048*2048).
// ---------------------------------------------------------------------------
extern "C" void kernel_launch(void* const* d_in, const int* in_sizes, int n_in,
                              void* d_out, int out_size)
{
    const float* hs = (const float*)d_in[0];
    const float* Wq = (const float*)d_in[1];
    const float* Wk = (const float*)d_in[2];
    const float* Wv = (const float*)d_in[3];

    float* ctx   = (float*)d_out;
    float* probs = ctx + (size_t)S_LEN * DM;

    cvt_x_kernel<<<dim3(S_LEN * DM / 4 / 256), 256>>>(hs);
    cvt_w_kernel<<<dim3(DM * DM / 4 / 256, 1, 3), 256>>>(Wq, Wk, Wv);
    qkv_gemm_kernel<<<dim3(DM / 64, S_LEN / 128, 3), 256>>>();
    scores_exp_kernel<<<dim3(S_LEN / 128, S_LEN / 128, NH), 256>>>();
    rowsum_kernel<<<dim3(NH * S_LEN / 256), 256>>>();
    pv_kernel<<<dim3(S_LEN / 128, NH), 256>>>(ctx);
    finalize_kernel<<<dim3(NH * S_LEN), 256>>>(probs);
}

// round 12
// speedup vs baseline: 1.1775x; 1.0289x over previous
#include <cuda_runtime.h>
#include <cuda_fp16.h>
#include <mma.h>
#include <math.h>
#include <cstdint>

using namespace nvcuda;

#define S_LEN 2048
#define DM    1024
#define NH    16
#define HD    64

// Scratch (allocation-guard rules: __device__ globals).
__device__ __half g_xh[S_LEN * DM];
__device__ __half g_wh[3][DM * DM];
__device__ __half g_qh[S_LEN * DM];
__device__ __half g_kh[S_LEN * DM];
__device__ __half g_vh[S_LEN * DM];
__device__ __half g_eh[(size_t)NH * S_LEN * S_LEN];  // unnormalized exp(scores), half
__device__ float  g_psum[(size_t)NH * S_LEN * 32];   // per-(row, ktile, wn) partials
__device__ float  g_rinv[NH * S_LEN];                // 1 / rowsum

// ---------------------------------------------------------------------------
// fp32 -> fp16 converters.
// ---------------------------------------------------------------------------
__device__ __forceinline__ void cvt4(const float* __restrict__ src,
                                     __half* __restrict__ dst, size_t i)
{
    float4 v = ((const float4*)src)[i];
    __half2 a = __floats2half2_rn(v.x, v.y);
    __half2 b = __floats2half2_rn(v.z, v.w);
    uint2 u;
    u.x = *(const uint32_t*)&a;
    u.y = *(const uint32_t*)&b;
    ((uint2*)dst)[i] = u;
}

__global__ __launch_bounds__(256) void cvt_x_kernel(const float* __restrict__ X)
{
    cvt4(X, g_xh, (size_t)blockIdx.x * 256 + threadIdx.x);
}

__global__ __launch_bounds__(256) void cvt_w_kernel(
    const float* __restrict__ Wq, const float* __restrict__ Wk,
    const float* __restrict__ Wv)
{
    const float* src = (blockIdx.z == 0) ? Wq : (blockIdx.z == 1) ? Wk : Wv;
    cvt4(src, g_wh[blockIdx.z], (size_t)blockIdx.x * 256 + threadIdx.x);
}

// ---------------------------------------------------------------------------
// Kernel 1: QKV projection (unchanged from round 11).
// ---------------------------------------------------------------------------
__global__ __launch_bounds__(256) void qkv_gemm_kernel()
{
    constexpr int BM = 128, BN = 64, BK = 32;
    const __half* W = g_wh[blockIdx.z];
    __half*       Y = (blockIdx.z == 0) ? g_qh : (blockIdx.z == 1) ? g_kh : g_vh;

    __shared__ __align__(16) union {
        struct { __half A[BM][BK + 8]; __half B[BK][BN + 8]; } in;
        float C[BM][BN + 4];
    } u;

    const int tid  = threadIdx.x;
    const int warp = tid >> 5;
    const int wm   = warp & 3;
    const int wn   = warp >> 2;

    const int row0 = blockIdx.y * BM;
    const int col0 = blockIdx.x * BN;

    wmma::fragment<wmma::accumulator, 16, 16, 16, float> acc[2][2];
    #pragma unroll
    for (int i = 0; i < 2; i++)
        #pragma unroll
        for (int j = 0; j < 2; j++)
            wmma::fill_fragment(acc[i][j], 0.0f);

    for (int k0 = 0; k0 < DM; k0 += BK) {
        #pragma unroll
        for (int it = 0; it < 2; it++) {
            int idx = tid + it * 256;
            int r = idx >> 2, c = idx & 3;
            *(int4*)&u.in.A[r][c * 8] =
                *(const int4*)&g_xh[(size_t)(row0 + r) * DM + k0 + c * 8];
        }
        {
            int r = tid >> 3, c = tid & 7;
            *(int4*)&u.in.B[r][c * 8] =
                *(const int4*)&W[(size_t)(k0 + r) * DM + col0 + c * 8];
        }
        __syncthreads();

        #pragma unroll
        for (int kk = 0; kk < BK; kk += 16) {
            wmma::fragment<wmma::matrix_a, 16, 16, 16, __half, wmma::row_major> a[2];
            wmma::fragment<wmma::matrix_b, 16, 16, 16, __half, wmma::row_major> b[2];
            #pragma unroll
            for (int i = 0; i < 2; i++)
                wmma::load_matrix_sync(a[i], &u.in.A[wm * 32 + i * 16][kk], BK + 8);
            #pragma unroll
            for (int j = 0; j < 2; j++)
                wmma::load_matrix_sync(b[j], &u.in.B[kk][wn * 32 + j * 16], BN + 8);
            #pragma unroll
            for (int i = 0; i < 2; i++)
                #pragma unroll
                for (int j = 0; j < 2; j++)
                    wmma::mma_sync(acc[i][j], a[i], b[j], acc[i][j]);
        }
        __syncthreads();
    }

    #pragma unroll
    for (int i = 0; i < 2; i++)
        #pragma unroll
        for (int j = 0; j < 2; j++)
            wmma::store_matrix_sync(&u.C[wm * 32 + i * 16][wn * 32 + j * 16],
                                    acc[i][j], BN + 4, wmma::mem_row_major);
    __syncthreads();

    #pragma unroll
    for (int it = 0; it < 8; it++) {
        int idx = tid + it * 256;
        int r = idx >> 4, c4 = idx & 15;
        float4 v = *(const float4*)&u.C[r][c4 * 4];
        __half2 h0 = __floats2half2_rn(v.x, v.y);
        __half2 h1 = __floats2half2_rn(v.z, v.w);
        uint2 o;
        o.x = *(const uint32_t*)&h0;
        o.y = *(const uint32_t*)&h1;
        *(uint2*)&Y[(size_t)(row0 + r) * DM + col0 + c4 * 4] = o;
    }
}

// ---------------------------------------------------------------------------
// Kernel 2: e = exp(q.k/8), raw mma.sync (unchanged from round 11).
// ---------------------------------------------------------------------------
__global__ __launch_bounds__(256) void scores_exp_kernel()
{
    const int h = blockIdx.z;
    __shared__ __align__(16) union {
        struct { __half Q[128][72]; __half K[128][72]; } in;
        __half E[128][136];
    } u;

    const int tid  = threadIdx.x;
    const int warp = tid >> 5;
    const int lane = tid & 31;
    const int wm   = warp & 3;
    const int wn   = warp >> 2;

    const int qrow0 = blockIdx.y * 128;
    const int krow0 = blockIdx.x * 128;
    const __half* qp = g_qh + h * HD;
    const __half* kp = g_kh + h * HD;

    #pragma unroll
    for (int it = 0; it < 4; it++) {
        int idx = tid + it * 256;
        int r = idx >> 3, c = idx & 7;
        *(int4*)&u.in.Q[r][c * 8] =
            *(const int4*)&qp[(size_t)(qrow0 + r) * DM + c * 8];
        *(int4*)&u.in.K[r][c * 8] =
            *(const int4*)&kp[(size_t)(krow0 + r) * DM + c * 8];
    }
    __syncthreads();

    float c[2][8][4];
    #pragma unroll
    for (int mi = 0; mi < 2; mi++)
        #pragma unroll
        for (int ni = 0; ni < 8; ni++)
            #pragma unroll
            for (int e = 0; e < 4; e++)
                c[mi][ni][e] = 0.0f;

    const uint32_t qs = (uint32_t)__cvta_generic_to_shared(&u.in.Q[0][0]);
    const uint32_t ks = (uint32_t)__cvta_generic_to_shared(&u.in.K[0][0]);
    const int lrow = lane & 15;
    const int lk   = (lane >> 4) * 8;

    #pragma unroll
    for (int kk = 0; kk < HD; kk += 16) {
        uint32_t a[2][4];
        #pragma unroll
        for (int mi = 0; mi < 2; mi++) {
            uint32_t addr = qs + (uint32_t)(((wm * 32 + mi * 16 + lrow) * 72 + kk + lk) * 2);
            asm volatile(
                "ldmatrix.sync.aligned.m8n8.x4.shared.b16 {%0,%1,%2,%3}, [%4];"
                : "=r"(a[mi][0]), "=r"(a[mi][1]), "=r"(a[mi][2]), "=r"(a[mi][3])
                : "r"(addr));
        }
        #pragma unroll
        for (int nb = 0; nb < 4; nb++) {
            uint32_t b0, b1, b2, b3;
            uint32_t addr = ks + (uint32_t)(((wn * 64 + nb * 16 + lrow) * 72 + kk + lk) * 2);
            asm volatile(
                "ldmatrix.sync.aligned.m8n8.x4.shared.b16 {%0,%1,%2,%3}, [%4];"
                : "=r"(b0), "=r"(b1), "=r"(b2), "=r"(b3)
                : "r"(addr));
            #pragma unroll
            for (int mi = 0; mi < 2; mi++) {
                asm volatile(
                    "mma.sync.aligned.m16n8k16.row.col.f32.f16.f16.f32 "
                    "{%0,%1,%2,%3}, {%4,%5,%6,%7}, {%8,%9}, {%0,%1,%2,%3};"
                    : "+f"(c[mi][2 * nb][0]), "+f"(c[mi][2 * nb][1]),
                      "+f"(c[mi][2 * nb][2]), "+f"(c[mi][2 * nb][3])
                    : "r"(a[mi][0]), "r"(a[mi][1]), "r"(a[mi][2]), "r"(a[mi][3]),
                      "r"(b0), "r"(b2));
                asm volatile(
                    "mma.sync.aligned.m16n8k16.row.col.f32.f16.f16.f32 "
                    "{%0,%1,%2,%3}, {%4,%5,%6,%7}, {%8,%9}, {%0,%1,%2,%3};"
                    : "+f"(c[mi][2 * nb + 1][0]), "+f"(c[mi][2 * nb + 1][1]),
                      "+f"(c[mi][2 * nb + 1][2]), "+f"(c[mi][2 * nb + 1][3])
                    : "r"(a[mi][0]), "r"(a[mi][1]), "r"(a[mi][2]), "r"(a[mi][3]),
                      "r"(b1), "r"(b3));
            }
        }
    }
    __syncthreads();

    #pragma unroll
    for (int mi = 0; mi < 2; mi++) {
        float sA = 0.0f, sB = 0.0f;
        #pragma unroll
        for (int ni = 0; ni < 8; ni++) {
            #pragma unroll
            for (int e = 0; e < 4; e++)
                c[mi][ni][e] = __expf(c[mi][ni][e] * 0.125f);
            sA += c[mi][ni][0] + c[mi][ni][1];
            sB += c[mi][ni][2] + c[mi][ni][3];
        }
        sA += __shfl_xor_sync(0xFFFFFFFFu, sA, 1);
        sA += __shfl_xor_sync(0xFFFFFFFFu, sA, 2);
        sB += __shfl_xor_sync(0xFFFFFFFFu, sB, 1);
        sB += __shfl_xor_sync(0xFFFFFFFFu, sB, 2);
        if ((lane & 3) == 0) {
            int r = wm * 32 + mi * 16 + (lane >> 2);
            g_psum[((size_t)h * S_LEN + qrow0 + r) * 32 + blockIdx.x * 2 + wn] = sA;
            g_psum[((size_t)h * S_LEN + qrow0 + r + 8) * 32 + blockIdx.x * 2 + wn] = sB;
        }
    }

    #pragma unroll
    for (int mi = 0; mi < 2; mi++)
        #pragma unroll
        for (int ni = 0; ni < 8; ni++) {
            int r   = wm * 32 + mi * 16 + (lane >> 2);
            int col = wn * 64 + ni * 8 + 2 * (lane & 3);
            __half2 lo = __floats2half2_rn(c[mi][ni][0], c[mi][ni][1]);
            __half2 hi = __floats2half2_rn(c[mi][ni][2], c[mi][ni][3]);
            *(__half2*)&u.E[r][col]     = lo;
            *(__half2*)&u.E[r + 8][col] = hi;
        }
    __syncthreads();

    __half* outp = g_eh + (size_t)h * S_LEN * S_LEN;
    #pragma unroll
    for (int it = 0; it < 8; it++) {
        int idx = tid + it * 256;
        int r = idx >> 4, cc = idx & 15;
        uint4 o = *(const uint4*)&u.E[r][cc * 8];
        *(uint4*)&outp[(size_t)(qrow0 + r) * S_LEN + krow0 + cc * 8] = o;
    }
}

// ---------------------------------------------------------------------------
// Kernel 3: rowsum -> reciprocal.
// ---------------------------------------------------------------------------
__global__ __launch_bounds__(256) void rowsum_kernel()
{
    int row = blockIdx.x * 256 + threadIdx.x;
    const float* p = &g_psum[(size_t)row * 32];
    float s = 0.0f;
    #pragma unroll
    for (int i = 0; i < 32; i++) s += p[i];
    g_rinv[row] = 1.0f / s;
}

// ---------------------------------------------------------------------------
// Kernel 4: finalize probs with streaming (__stwt) stores.
// ---------------------------------------------------------------------------
__global__ __launch_bounds__(256) void finalize_kernel(float* __restrict__ probs)
{
    const size_t row = blockIdx.x;
    const float rinv = g_rinv[row];
    const uint4* src = (const uint4*)(g_eh + row * S_LEN);
    float4* dst = (float4*)(probs + row * S_LEN);
    const int tid = threadIdx.x;

    uint4 uv = src[tid];
    __half2 h0 = *(const __half2*)&uv.x;
    __half2 h1 = *(const __half2*)&uv.y;
    __half2 h2 = *(const __half2*)&uv.z;
    __half2 h3 = *(const __half2*)&uv.w;
    float2 f0 = __half22float2(h0);
    float2 f1 = __half22float2(h1);
    float2 f2 = __half22float2(h2);
    float2 f3 = __half22float2(h3);
    __stwt(&dst[2 * tid],
           make_float4(f0.x * rinv, f0.y * rinv, f1.x * rinv, f1.y * rinv));
    __stwt(&dst[2 * tid + 1],
           make_float4(f2.x * rinv, f2.y * rinv, f3.x * rinv, f3.y * rinv));
}

// ---------------------------------------------------------------------------
// Kernel 5: PV, raw mma.sync.m16n8k16. A = e (ldmatrix.x4), B = V
// (ldmatrix.x2.trans). Register epilogue: rinv scale + direct float2 stores.
// BM=128, BK=64. 8 warps (4 m-strips x 2 n-strips of 32 cols).
// ---------------------------------------------------------------------------
__global__ __launch_bounds__(256) void pv_kernel(float* __restrict__ ctx)
{
    constexpr int BM = 128, BK = 64;
    const int h = blockIdx.y;
    const __half* E  = g_eh + (size_t)h * S_LEN * S_LEN;
    const __half* vp = g_vh + h * HD;

    __shared__ __align__(16) __half Ps[BM][BK + 8];   // 128 x 72
    __shared__ __align__(16) __half Vs[BK][HD + 8];   // 64 x 72
    __shared__ float rinv[BM];

    const int tid  = threadIdx.x;
    const int warp = tid >> 5;
    const int lane = tid & 31;
    const int wm   = warp & 3;   // 4 strips of 32 rows
    const int wn   = warp >> 2;  // 2 strips of 32 cols
    const int row0 = blockIdx.x * BM;

    if (tid < BM)
        rinv[tid] = g_rinv[(size_t)h * S_LEN + row0 + tid];

    float c[2][4][4];
    #pragma unroll
    for (int mi = 0; mi < 2; mi++)
        #pragma unroll
        for (int ni = 0; ni < 4; ni++)
            #pragma unroll
            for (int e = 0; e < 4; e++)
                c[mi][ni][e] = 0.0f;

    const uint32_t ps = (uint32_t)__cvta_generic_to_shared(&Ps[0][0]);
    const uint32_t vs = (uint32_t)__cvta_generic_to_shared(&Vs[0][0]);
    const int lrow = lane & 15;
    const int lk   = (lane >> 4) * 8;

    for (int k0 = 0; k0 < S_LEN; k0 += BK) {
        // P tile: 128 rows x 8 int4 = 1024, 4/thread
        #pragma unroll
        for (int it = 0; it < 4; it++) {
            int idx = tid + it * 256;
            int r = idx >> 3, cc = idx & 7;
            *(int4*)&Ps[r][cc * 8] =
                *(const int4*)&E[(size_t)(row0 + r) * S_LEN + k0 + cc * 8];
        }
        // V tile: 64 rows x 8 int4 = 512, 2/thread
        #pragma unroll
        for (int it = 0; it < 2; it++) {
            int idx = tid + it * 256;
            int r = idx >> 3, cc = idx & 7;
            *(int4*)&Vs[r][cc * 8] =
                *(const int4*)&vp[(size_t)(k0 + r) * DM + cc * 8];
        }
        __syncthreads();

        #pragma unroll
        for (int kk = 0; kk < BK; kk += 16) {
            uint32_t a[2][4];
            #pragma unroll
            for (int mi = 0; mi < 2; mi++) {
                uint32_t addr = ps + (uint32_t)(((wm * 32 + mi * 16 + lrow) * 72 + kk + lk) * 2);
                asm volatile(
                    "ldmatrix.sync.aligned.m8n8.x4.shared.b16 {%0,%1,%2,%3}, [%4];"
                    : "=r"(a[mi][0]), "=r"(a[mi][1]), "=r"(a[mi][2]), "=r"(a[mi][3])
                    : "r"(addr));
            }
            #pragma unroll
            for (int ni = 0; ni < 4; ni++) {
                uint32_t b0, b1;
                // B: V[k][n] row-major -> col fragment via trans ldmatrix.
                // 16 addresses (lanes 0-15) = k rows kk..kk+15, col block n0.
                uint32_t addr = vs + (uint32_t)(((kk + lrow) * 72 + wn * 32 + ni * 8) * 2);
                asm volatile(
                    "ldmatrix.sync.aligned.m8n8.x2.trans.shared.b16 {%0,%1}, [%2];"
                    : "=r"(b0), "=r"(b1)
                    : "r"(addr));
                #pragma unroll
                for (int mi = 0; mi < 2; mi++) {
                    asm volatile(
                        "mma.sync.aligned.m16n8k16.row.col.f32.f16.f16.f32 "
                        "{%0,%1,%2,%3}, {%4,%5,%6,%7}, {%8,%9}, {%0,%1,%2,%3};"
                        : "+f"(c[mi][ni][0]), "+f"(c[mi][ni][1]),
                          "+f"(c[mi][ni][2]), "+f"(c[mi][ni][3])
                        : "r"(a[mi][0]), "r"(a[mi][1]), "r"(a[mi][2]), "r"(a[mi][3]),
                          "r"(b0), "r"(b1));
                }
            }
        }
        __syncthreads();
    }

    // Register epilogue: scale rows by rinv, direct stores.
    #pragma unroll
    for (int mi = 0; mi < 2; mi++) {
        int rloc0 = wm * 32 + mi * 16 + (lane >> 2);
        int rloc1 = rloc0 + 8;
        float iv0 = rinv[rloc0];
        float iv1 = rinv[rloc1];
        #pragma unroll
        for (int ni = 0; ni < 4; ni++) {
            int col = h * HD + wn * 32 + ni * 8 + 2 * (lane & 3);
            *(float2*)&ctx[(size_t)(row0 + rloc0) * DM + col] =
                make_float2(c[mi][ni][0] * iv0, c[mi][ni][1] * iv0);
            *(float2*)&ctx[(size_t)(row0 + rloc1) * DM + col] =
                make_float2(c[mi][ni][2] * iv1, c[mi][ni][3] * iv1);
        }
    }
}

// ---------------------------------------------------------------------------
// Launch. d_out layout: context (2048*1024 floats) then probs (16*2048*2048).
// ---------------------------------------------------------------------------
extern "C" void kernel_launch(void* const* d_in, const int* in_sizes, int n_in,
                              void* d_out, int out_size)
{
    const float* hs = (const float*)d_in[0];
    const float* Wq = (const float*)d_in[1];
    const float* Wk = (const float*)d_in[2];
    const float* Wv = (const float*)d_in[3];

    float* ctx   = (float*)d_out;
    float* probs = ctx + (size_t)S_LEN * DM;

    cvt_x_kernel<<<dim3(S_LEN * DM / 4 / 256), 256>>>(hs);
    cvt_w_kernel<<<dim3(DM * DM / 4 / 256, 1, 3), 256>>>(Wq, Wk, Wv);
    qkv_gemm_kernel<<<dim3(DM / 64, S_LEN / 128, 3), 256>>>();
    scores_exp_kernel<<<dim3(S_LEN / 128, S_LEN / 128, NH), 256>>>();
    rowsum_kernel<<<dim3(NH * S_LEN / 256), 256>>>();
    pv_kernel<<<dim3(S_LEN / 128, NH), 256>>>(ctx);
    finalize_kernel<<<dim3(NH * S_LEN), 256>>>(probs);
}